// round 3
// baseline (speedup 1.0000x reference)
#include <cuda_runtime.h>
#include <cstdint>

// ---------------------------------------------------------------------------
// Problem constants
#define B_    32
#define C_    256
#define H_    58
#define W_    58
#define HW_   3364
#define OC_   256
#define HO_   56
#define WO_   56
#define NINPUT 861184.0f     // C*H*W (alpha normalizer, per reference)

// Scratch (device globals; allocations forbidden)
// x in NHWC as int8 {-1,+1}; +64 pixels of slack for tap-shift overreads.
__device__ __align__(256) char  g_xb[(B_ * HW_ + 64) * C_];    // ~27.6 MB
// weights as int8 {-1,+1}: [tap][o][c]
__device__ __align__(256) char  g_wb[9 * OC_ * C_];            // 590 KB
__device__ float g_alpha[OC_];

// ---------------------------------------------------------------------------
#define CPA16(dst, src) \
    asm volatile("cp.async.cg.shared.global [%0], [%1], 16;" :: "r"(dst), "l"(src))

__device__ __forceinline__ uint32_t smem_u32(const void* p) {
    uint32_t a;
    asm("{ .reg .u64 t; cvta.to.shared.u64 t, %1; cvt.u32.u64 %0, t; }"
        : "=r"(a) : "l"(p));
    return a;
}

// s8 x s8 -> s32 tensor-core MMA (family-common PTX, sm_80+)
__device__ __forceinline__ void mma_s8(int* d,
                                       unsigned a0, unsigned a1, unsigned a2, unsigned a3,
                                       unsigned b0, unsigned b1) {
    asm volatile(
        "mma.sync.aligned.m16n8k32.row.col.s32.s8.s8.s32 "
        "{%0,%1,%2,%3}, {%4,%5,%6,%7}, {%8,%9}, {%0,%1,%2,%3};"
        : "+r"(d[0]), "+r"(d[1]), "+r"(d[2]), "+r"(d[3])
        : "r"(a0), "r"(a1), "r"(a2), "r"(a3), "r"(b0), "r"(b1));
}

// ---------------------------------------------------------------------------
// Pass 1: x (NCHW fp32 {0,1}) -> g_xb (NHWC int8 {-1,+1}) via smem transpose
// grid = (53, 32), block = 256. Tile = 64 pixels x 256 channels.
// ---------------------------------------------------------------------------
__global__ void pack_xb_kernel(const float* __restrict__ x) {
    int b    = blockIdx.y;
    int pos0 = blockIdx.x * 64;
    __shared__ char tile[64 * 260];
    int tid = threadIdx.x;

    for (int idx = tid; idx < 64 * 256; idx += 256) {
        int c = idx >> 6, p = idx & 63;
        int pos = pos0 + p;
        float v = 0.f;
        if (pos < HW_) v = x[((size_t)b * C_ + c) * HW_ + pos];
        tile[p * 260 + c] = (v > 0.5f) ? (char)1 : (char)-1;
    }
    __syncthreads();
    for (int idx = tid; idx < 64 * 64; idx += 256) {
        int p = idx >> 6, cc = idx & 63;
        int pos = pos0 + p;
        if (pos < HW_) {
            unsigned v = *(const unsigned*)&tile[p * 260 + cc * 4];
            *(unsigned*)&g_xb[((size_t)b * HW_ + pos) * C_ + cc * 4] = v;
        }
    }
}

// ---------------------------------------------------------------------------
// Pass 2: weights -> g_wb (int8 {-1,+1}, [tap][o][c]) + alpha[o]
// ---------------------------------------------------------------------------
__global__ void pack_wb_kernel(const float* __restrict__ wgt) {
    int o = blockIdx.x, c = threadIdx.x;
    const float* wp = wgt + ((size_t)o * C_ + c) * 9;
    float asum = 0.f;
#pragma unroll
    for (int k = 0; k < 9; k++) {
        float v = wp[k];
        asum += fabsf(v);
        g_wb[(size_t)k * (OC_ * C_) + o * C_ + c] = (v >= 0.f) ? (char)1 : (char)-1;
    }
    __shared__ float red[256];
    red[c] = asum;
    __syncthreads();
#pragma unroll
    for (int s = 128; s > 0; s >>= 1) {
        if (c < s) red[c] += red[c + s];
        __syncthreads();
    }
    if (c == 0) g_alpha[o] = red[0] / NINPUT;
}

// ---------------------------------------------------------------------------
// Pass 3: implicit-GEMM XNOR conv on s8 mma.sync.
// One CTA = (batch b, output-row pair y0,y0+1): M=128 (m = ry*64+xx, xx<56 valid),
// N=256 output channels, K=2304 as 18 chunks of 128 (tap-half-channels).
// 512 threads = 16 warps in 4(M) x 4(N); per warp 32x64 outputs.
// Smem row stride 144B (128B payload + 16B pad) -> all fragment LDS conflict-free.
// ---------------------------------------------------------------------------
#define SROW   144
#define A_BYTES (128 * SROW)            // 18432
#define B_BYTES (256 * SROW)            // 36864
#define STAGE  (A_BYTES + B_BYTES)      // 55296
#define NSLOT  4
#define SM_ALPHA (NSLOT * STAGE)        // 221184
#define SM_TOTAL (SM_ALPHA + 1024)      // 222208

__device__ __forceinline__ void issue_stage(int tid, int b, int y0, int st,
                                            uint32_t aslot, uint32_t bslot) {
    int tap = st >> 1, c0 = (st & 1) * 128;
    int kh = tap / 3, kw = tap % 3;
    const char* xb = g_xb + (size_t)b * HW_ * C_;
#pragma unroll
    for (int t = 0; t < 2; t++) {                 // A: 1024 x 16B chunks
        int idx = tid + t * 512;
        int row = idx >> 3, i = idx & 7;
        int ry = row >> 6, xx = row & 63;
        int pix = (y0 + ry + kh) * W_ + kw + xx;
        const void* src = xb + (size_t)pix * C_ + c0 + i * 16;
        CPA16(aslot + row * SROW + i * 16, src);
    }
    const char* wb = g_wb + (size_t)tap * (OC_ * C_) + c0;
#pragma unroll
    for (int t = 0; t < 4; t++) {                 // B: 2048 x 16B chunks
        int idx = tid + t * 512;
        int row = idx >> 3, i = idx & 7;
        const void* src = wb + (size_t)row * C_ + i * 16;
        CPA16(bslot + row * SROW + i * 16, src);
    }
}

__global__ void __launch_bounds__(512, 1)
xnor_imma_kernel(float* __restrict__ out) {
    extern __shared__ char smem[];
    uint32_t sb = smem_u32(smem);
    int tid = threadIdx.x;
    int wid = tid >> 5, lane = tid & 31;
    int mw = wid >> 2, nw = wid & 3;              // warp grid 4(M) x 4(N)
    int lo4 = lane >> 2, l4 = lane & 3;

    int bid = blockIdx.x;
    int b = bid / 28, y0 = (bid % 28) * 2;

    float* sal = (float*)(smem + SM_ALPHA);
    for (int i = tid; i < 256; i += 512) sal[i] = g_alpha[i];

    // Prologue: 3 stages in flight (4th slot keeps issue-ahead safe)
#pragma unroll
    for (int s = 0; s < 3; s++) {
        issue_stage(tid, b, y0, s, sb + (s % NSLOT) * STAGE,
                    sb + (s % NSLOT) * STAGE + A_BYTES);
        asm volatile("cp.async.commit_group;" ::: "memory");
    }

    int acc[2][8][4];
#pragma unroll
    for (int mt = 0; mt < 2; mt++)
#pragma unroll
        for (int nt = 0; nt < 8; nt++)
#pragma unroll
            for (int r = 0; r < 4; r++) acc[mt][nt][r] = 0;

    for (int s = 0; s < 18; s++) {
        int slot = s & 3;
        if (s < 15) { asm volatile("cp.async.wait_group 2;" ::: "memory"); }
        else        { asm volatile("cp.async.wait_group 0;" ::: "memory"); }
        __syncthreads();
        if (s + 3 < 18) {
            int ns = (s + 3) & 3;
            issue_stage(tid, b, y0, s + 3, sb + ns * STAGE,
                        sb + ns * STAGE + A_BYTES);
            asm volatile("cp.async.commit_group;" ::: "memory");
        }

        const char* As = smem + slot * STAGE;
        const char* Bs = As + A_BYTES;

#pragma unroll
        for (int ks = 0; ks < 4; ks++) {
            int kk = ks * 32 + l4 * 4;
            // A fragments: 2 m-tiles (m16), rows = mw*32 + mt*16 + lo4 (+8)
            unsigned a[2][4];
#pragma unroll
            for (int mt = 0; mt < 2; mt++) {
                const char* ap = As + (mw * 32 + mt * 16 + lo4) * SROW + kk;
                a[mt][0] = *(const unsigned*)(ap);
                a[mt][1] = *(const unsigned*)(ap + 8 * SROW);
                a[mt][2] = *(const unsigned*)(ap + 16);
                a[mt][3] = *(const unsigned*)(ap + 8 * SROW + 16);
            }
            // B fragments: 8 n-tiles (n8), rows = nw*64 + nt*8 + lo4
            unsigned bf[8][2];
#pragma unroll
            for (int nt = 0; nt < 8; nt++) {
                const char* bp = Bs + (nw * 64 + nt * 8 + lo4) * SROW + kk;
                bf[nt][0] = *(const unsigned*)(bp);
                bf[nt][1] = *(const unsigned*)(bp + 16);
            }
#pragma unroll
            for (int mt = 0; mt < 2; mt++)
#pragma unroll
                for (int nt = 0; nt < 8; nt++)
                    mma_s8(acc[mt][nt], a[mt][0], a[mt][1], a[mt][2], a[mt][3],
                           bf[nt][0], bf[nt][1]);
        }
        __syncthreads();
    }

    // Epilogue: acc (exact 2S - CN) -> alpha[o] * acc
#pragma unroll
    for (int mt = 0; mt < 2; mt++) {
#pragma unroll
        for (int half = 0; half < 2; half++) {
            int m = mw * 32 + mt * 16 + lo4 + half * 8;
            int ry = m >> 6, xx = m & 63;
            if (xx < 56) {
                float* op = out + (size_t)b * (OC_ * HO_ * WO_)
                                + (size_t)(y0 + ry) * WO_ + xx;
#pragma unroll
                for (int nt = 0; nt < 8; nt++) {
                    int col = nw * 64 + nt * 8 + l4 * 2;
                    op[(size_t)col * (HO_ * WO_)] =
                        sal[col] * (float)acc[mt][nt][half * 2 + 0];
                    op[(size_t)(col + 1) * (HO_ * WO_)] =
                        sal[col + 1] * (float)acc[mt][nt][half * 2 + 1];
                }
            }
        }
    }
}

// ---------------------------------------------------------------------------
extern "C" void kernel_launch(void* const* d_in, const int* in_sizes, int n_in,
                              void* d_out, int out_size) {
    const float* x   = (const float*)d_in[0];
    const float* wgt = (const float*)d_in[1];
    float* out = (float*)d_out;

    cudaFuncSetAttribute(xnor_imma_kernel,
                         cudaFuncAttributeMaxDynamicSharedMemorySize, SM_TOTAL);

    dim3 g1((HW_ + 63) / 64, B_);
    pack_xb_kernel<<<g1, 256>>>(x);
    pack_wb_kernel<<<OC_, 256>>>(wgt);
    xnor_imma_kernel<<<B_ * (HO_ / 2), 512, SM_TOTAL>>>(out);
}

// round 4
// speedup vs baseline: 2.4027x; 2.4027x over previous
#include <cuda_runtime.h>
#include <cstdint>

// Problem constants
#define B_   32
#define C_   256
#define H_   58
#define W_   58
#define OC_  256
#define KH_  3
#define KW_  3
#define HO_  56
#define WO_  56
#define HW_  (H_*W_)            // 3364
#define NWORDS 8                // 256 channels / 32 bits
#define CN_  2304               // C*KH*KW
#define NINPUT 861184.0f        // C*H*W (alpha normalizer)

// Scratch (device globals; no allocations allowed)
__device__ unsigned g_xpack[B_ * HW_ * NWORDS];        // [b][y][x][w]  3.44 MB
__device__ unsigned g_wpack[OC_ * KH_ * KW_ * NWORDS]; // [o][k][w]     73.7 KB
__device__ float    g_alpha[OC_];

// ---------------------------------------------------------------------------
// Pass 1: pack binary activations over the channel dimension. (HBM-roofline)
// ---------------------------------------------------------------------------
__global__ void pack_x_kernel(const float* __restrict__ x) {
    int bw = blockIdx.x;
    int b  = bw >> 3;
    int w  = bw & 7;
    int pos = blockIdx.y * blockDim.x + threadIdx.x;
    if (pos >= HW_) return;

    const float* xp = x + ((size_t)(b * C_ + w * 32) * HW_) + pos;
    unsigned bits = 0;
#pragma unroll
    for (int c = 0; c < 32; c++) {
        float v = __ldg(xp + (size_t)c * HW_);
        bits |= (v > 0.5f ? 1u : 0u) << c;
    }
    g_xpack[((size_t)b * HW_ + pos) * NWORDS + w] = bits;
}

// ---------------------------------------------------------------------------
// Pass 2: pack binarized weights (ballot) + alpha per filter.
// ---------------------------------------------------------------------------
__global__ void pack_w_kernel(const float* __restrict__ wgt) {
    int o = blockIdx.x;
    int c = threadIdx.x;
    int lane = c & 31;
    int wrp  = c >> 5;

    const float* wp = wgt + (size_t)(o * C_ + c) * (KH_ * KW_);
    float asum = 0.f;
#pragma unroll
    for (int k = 0; k < KH_ * KW_; k++) {
        float v = wp[k];
        asum += fabsf(v);
        unsigned word = __ballot_sync(0xffffffffu, v >= 0.f);
        if (lane == 0) g_wpack[(o * 9 + k) * NWORDS + wrp] = word;
    }

    __shared__ float red[256];
    red[c] = asum;
    __syncthreads();
#pragma unroll
    for (int s = 128; s > 0; s >>= 1) {
        if (c < s) red[c] += red[c + s];
        __syncthreads();
    }
    if (c == 0) g_alpha[o] = red[0] / NINPUT;
}

// ---------------------------------------------------------------------------
// 8-word XNOR-popcount accumulate with IADD3-friendly reduction tree:
// 8 LOP3 + 8 POPC + 4 IADD3 (vs 8 serial IADDs before).
// ---------------------------------------------------------------------------
__device__ __forceinline__ int acc8(int P, uint4 lo, uint4 hi,
                                    const unsigned* __restrict__ w) {
    int a = __popc(lo.x ^ w[0]);
    int b = __popc(lo.y ^ w[1]);
    int c = __popc(lo.z ^ w[2]);
    int d = __popc(lo.w ^ w[3]);
    int e = __popc(hi.x ^ w[4]);
    int f = __popc(hi.y ^ w[5]);
    int g = __popc(hi.z ^ w[6]);
    int h = __popc(hi.w ^ w[7]);
    return ((a + b + c) + (d + e + f)) + (g + h + P);
}

// ---------------------------------------------------------------------------
// Pass 3: XNOR-popcount conv.
// grid = B_*HO_ (block = (batch, output row)), block = 256 (thread = o).
// Packed-x 3-row window in smem (broadcast reads); 72 weight words in regs.
// 4 outputs per step; each shared pixel column feeds all valid kw taps.
// ---------------------------------------------------------------------------
__global__ void __launch_bounds__(256, 2)
xnor_conv_kernel(float* __restrict__ out) {
    int by = blockIdx.x;
    int b  = by / HO_;
    int y  = by % HO_;
    int o  = threadIdx.x;

    __shared__ __align__(16) unsigned sx[3 * W_ * NWORDS]; // 5568 B

    const int ROW4 = W_ * NWORDS / 4; // 116 uint4 per row
    for (int i = threadIdx.x; i < 3 * ROW4; i += 256) {
        int kh = i / ROW4;
        int r  = i - kh * ROW4;
        const uint4* src = (const uint4*)(g_xpack + ((size_t)(b * H_ + y + kh) * W_) * NWORDS);
        ((uint4*)sx)[kh * ROW4 + r] = src[r];
    }

    unsigned wt[72];
    {
        const uint4* wp4 = (const uint4*)(g_wpack + o * 72);
#pragma unroll
        for (int i = 0; i < 18; i++) ((uint4*)wt)[i] = wp4[i];
    }
    float a = g_alpha[o];
    __syncthreads();

    float* outp = out + ((size_t)(b * OC_ + o) * HO_ + y) * WO_;

    for (int x0 = 0; x0 < WO_; x0 += 4) {
        int P0 = 0, P1 = 0, P2 = 0, P3 = 0;
#pragma unroll
        for (int kh = 0; kh < 3; kh++) {
#pragma unroll
            for (int j = 0; j < 6; j++) {          // 6 pixel columns feed 4 outputs
                const uint4* px = (const uint4*)&sx[(kh * W_ + x0 + j) * NWORDS];
                uint4 lo = px[0];
                uint4 hi = px[1];
#pragma unroll
                for (int kw = 0; kw < 3; kw++) {
                    int xi = j - kw;
                    if (xi >= 0 && xi < 4) {
                        const unsigned* ww = &wt[(kh * 3 + kw) * NWORDS];
                        if      (xi == 0) P0 = acc8(P0, lo, hi, ww);
                        else if (xi == 1) P1 = acc8(P1, lo, hi, ww);
                        else if (xi == 2) P2 = acc8(P2, lo, hi, ww);
                        else              P3 = acc8(P3, lo, hi, ww);
                    }
                }
            }
        }
        float4 r;
        r.x = a * (float)(CN_ - 2 * P0);
        r.y = a * (float)(CN_ - 2 * P1);
        r.z = a * (float)(CN_ - 2 * P2);
        r.w = a * (float)(CN_ - 2 * P3);
        *(float4*)(outp + x0) = r;
    }
}

// ---------------------------------------------------------------------------
extern "C" void kernel_launch(void* const* d_in, const int* in_sizes, int n_in,
                              void* d_out, int out_size) {
    const float* x   = (const float*)d_in[0];
    const float* wgt = (const float*)d_in[1];
    float* out = (float*)d_out;

    dim3 g1(B_ * NWORDS, (HW_ + 255) / 256);
    pack_x_kernel<<<g1, 256>>>(x);
    pack_w_kernel<<<OC_, 256>>>(wgt);
    xnor_conv_kernel<<<B_ * HO_, 256>>>(out);
}

// round 5
// speedup vs baseline: 2.9245x; 1.2172x over previous
#include <cuda_runtime.h>
#include <cstdint>

// Problem constants
#define B_   32
#define C_   256
#define H_   58
#define W_   58
#define OC_  256
#define KH_  3
#define KW_  3
#define HO_  56
#define WO_  56
#define HW_  (H_*W_)            // 3364
#define NWORDS 8                // 256 channels / 32 bits
#define CN_  2304               // C*KH*KW
#define NINPUT 861184.0f        // C*H*W (alpha normalizer)

// Scratch (device globals; no allocations allowed)
__device__ unsigned g_xpack[B_ * HW_ * NWORDS];        // [b][y][x][w]  3.44 MB
__device__ unsigned g_wpack[OC_ * KH_ * KW_ * NWORDS]; // [o][k][w]     73.7 KB
__device__ float    g_alpha[OC_];

// ---------------------------------------------------------------------------
// Pass 1: pack binary activations over the channel dimension. (HBM-roofline)
// ---------------------------------------------------------------------------
__global__ void pack_x_kernel(const float* __restrict__ x) {
    int bw = blockIdx.x;
    int b  = bw >> 3;
    int w  = bw & 7;
    int pos = blockIdx.y * blockDim.x + threadIdx.x;
    if (pos >= HW_) return;

    const float* xp = x + ((size_t)(b * C_ + w * 32) * HW_) + pos;
    unsigned bits = 0;
#pragma unroll
    for (int c = 0; c < 32; c++) {
        float v = __ldg(xp + (size_t)c * HW_);
        bits |= (v > 0.5f ? 1u : 0u) << c;
    }
    g_xpack[((size_t)b * HW_ + pos) * NWORDS + w] = bits;
}

// ---------------------------------------------------------------------------
// Pass 2: pack binarized weights (ballot) + alpha per filter.
// ---------------------------------------------------------------------------
__global__ void pack_w_kernel(const float* __restrict__ wgt) {
    int o = blockIdx.x;
    int c = threadIdx.x;
    int lane = c & 31;
    int wrp  = c >> 5;

    const float* wp = wgt + (size_t)(o * C_ + c) * (KH_ * KW_);
    float asum = 0.f;
#pragma unroll
    for (int k = 0; k < KH_ * KW_; k++) {
        float v = wp[k];
        asum += fabsf(v);
        unsigned word = __ballot_sync(0xffffffffu, v >= 0.f);
        if (lane == 0) g_wpack[(o * 9 + k) * NWORDS + wrp] = word;
    }

    __shared__ float red[256];
    red[c] = asum;
    __syncthreads();
#pragma unroll
    for (int s = 128; s > 0; s >>= 1) {
        if (c < s) red[c] += red[c + s];
        __syncthreads();
    }
    if (c == 0) g_alpha[o] = red[0] / NINPUT;
}

// ---------------------------------------------------------------------------
// Pass 3: XNOR-popcount conv with full-adder (CSA) compression over kw taps.
//
// For output x, row kh, word w, the three taps give
//   popc(x)+popc(y)+popc(z) = popc(u) + 2*popc(v)
// with u = s3 ^ wx3   (s3 = p0^p1^p2 precomputed in smem, shared by all o;
//                      wx3 = w0^w1^w2 precomputed per thread)
//      v = maj(x,y,z) = (x&y) | ((x^y) & ~u)   [z never materialized]
// -> 4 LOP3 + 2 POPC per (kh,word) instead of 3 LOP3 + 3 POPC.
// grid = B_*HO_, block = 256 (thread = output channel o), 4 outputs/step.
// ---------------------------------------------------------------------------
__global__ void __launch_bounds__(256, 2)
xnor_conv_kernel(float* __restrict__ out) {
    int by = blockIdx.x;
    int b  = by / HO_;
    int y  = by % HO_;
    int o  = threadIdx.x;

    __shared__ __align__(16) unsigned sx[3 * W_  * NWORDS];  // 5568 B
    __shared__ __align__(16) unsigned s3[3 * WO_ * NWORDS];  // 5376 B

    // load 3 packed rows
    const int ROW4 = W_ * NWORDS / 4; // 116 uint4 per row
    for (int i = threadIdx.x; i < 3 * ROW4; i += 256) {
        int kh = i / ROW4;
        int r  = i - kh * ROW4;
        const uint4* src = (const uint4*)(g_xpack + ((size_t)(b * H_ + y + kh) * W_) * NWORDS);
        ((uint4*)sx)[kh * ROW4 + r] = src[r];
    }

    // per-thread weights: kw0, kw1, and the tap-XOR3 (kw2 folded into wx3)
    unsigned w0[24], w1[24], wx3[24];
    {
        const uint4* wp4 = (const uint4*)(g_wpack + o * 72);
#pragma unroll
        for (int kh = 0; kh < 3; kh++) {
            uint4 a0 = wp4[(kh * 3 + 0) * 2],     a1 = wp4[(kh * 3 + 0) * 2 + 1];
            uint4 b0 = wp4[(kh * 3 + 1) * 2],     b1 = wp4[(kh * 3 + 1) * 2 + 1];
            uint4 c0 = wp4[(kh * 3 + 2) * 2],     c1 = wp4[(kh * 3 + 2) * 2 + 1];
            ((uint4*)w0)[kh * 2]     = a0; ((uint4*)w0)[kh * 2 + 1] = a1;
            ((uint4*)w1)[kh * 2]     = b0; ((uint4*)w1)[kh * 2 + 1] = b1;
            wx3[kh * 8 + 0] = a0.x ^ b0.x ^ c0.x;
            wx3[kh * 8 + 1] = a0.y ^ b0.y ^ c0.y;
            wx3[kh * 8 + 2] = a0.z ^ b0.z ^ c0.z;
            wx3[kh * 8 + 3] = a0.w ^ b0.w ^ c0.w;
            wx3[kh * 8 + 4] = a1.x ^ b1.x ^ c1.x;
            wx3[kh * 8 + 5] = a1.y ^ b1.y ^ c1.y;
            wx3[kh * 8 + 6] = a1.z ^ b1.z ^ c1.z;
            wx3[kh * 8 + 7] = a1.w ^ b1.w ^ c1.w;
        }
    }
    float a = g_alpha[o];
    __syncthreads();

    // precompute s3[kh][c][w] = sx[kh][c] ^ sx[kh][c+1] ^ sx[kh][c+2]
    for (int i = threadIdx.x; i < 3 * WO_ * NWORDS; i += 256) {
        int kh = i / (WO_ * NWORDS);
        int r  = i - kh * (WO_ * NWORDS);        // c*8 + w
        int base = kh * (W_ * NWORDS) + r;
        s3[i] = sx[base] ^ sx[base + NWORDS] ^ sx[base + 2 * NWORDS];
    }
    __syncthreads();

    float* outp = out + ((size_t)(b * OC_ + o) * HO_ + y) * WO_;

    for (int x0 = 0; x0 < WO_; x0 += 4) {
        int Pu[4] = {0, 0, 0, 0};
        int Pv[4] = {0, 0, 0, 0};
#pragma unroll
        for (int kh = 0; kh < 3; kh++) {
#pragma unroll
            for (int half = 0; half < 2; half++) {
                // 5 pixel columns (kw=0 and kw=1 roles), 4 words each
                uint4 p[5];
#pragma unroll
                for (int c = 0; c < 5; c++)
                    p[c] = *(const uint4*)&sx[(kh * W_ + x0 + c) * NWORDS + half * 4];
                const unsigned* pw = (const unsigned*)p;
#pragma unroll
                for (int xi = 0; xi < 4; xi++) {
                    uint4 s = *(const uint4*)&s3[(kh * WO_ + x0 + xi) * NWORDS + half * 4];
                    unsigned sv[4] = {s.x, s.y, s.z, s.w};
                    int su = 0, svv = 0;
#pragma unroll
                    for (int j = 0; j < 4; j++) {
                        int wi = kh * 8 + half * 4 + j;
                        unsigned u  = sv[j] ^ wx3[wi];
                        unsigned xw = pw[xi * 4 + j] ^ w0[wi];
                        unsigned yw = pw[(xi + 1) * 4 + j] ^ w1[wi];
                        unsigned v  = (xw & yw) | ((xw ^ yw) & ~u);
                        su  += __popc(u);
                        svv += __popc(v);
                    }
                    Pu[xi] += su;
                    Pv[xi] += svv;
                }
            }
        }
        float4 r;
        r.x = a * (float)(CN_ - 2 * (Pu[0] + 2 * Pv[0]));
        r.y = a * (float)(CN_ - 2 * (Pu[1] + 2 * Pv[1]));
        r.z = a * (float)(CN_ - 2 * (Pu[2] + 2 * Pv[2]));
        r.w = a * (float)(CN_ - 2 * (Pu[3] + 2 * Pv[3]));
        *(float4*)(outp + x0) = r;
    }
}

// ---------------------------------------------------------------------------
extern "C" void kernel_launch(void* const* d_in, const int* in_sizes, int n_in,
                              void* d_out, int out_size) {
    const float* x   = (const float*)d_in[0];
    const float* wgt = (const float*)d_in[1];
    float* out = (float*)d_out;

    dim3 g1(B_ * NWORDS, (HW_ + 255) / 256);
    pack_x_kernel<<<g1, 256>>>(x);
    pack_w_kernel<<<OC_, 256>>>(wgt);
    xnor_conv_kernel<<<B_ * HO_, 256>>>(out);
}